// round 12
// baseline (speedup 1.0000x reference)
#include <cuda_runtime.h>
#include <cuda_fp16.h>
#include <cstdint>
#include <cfloat>

#define W_TOTAL   262144
#define L_DIM     512
#define G_DIM     128
#define TILE_ROWS 128
#define NUM_TILES (W_TOTAL / TILE_ROWS)   // 2048
#define NKCH      4                       // K chunks of 128
#define NTHREADS  512
#define NUM_CTAS  148                     // persistent, all resident (<= SM count)

// ---- smem layout (bytes), dynamic smem only ----
#define OFF_B      0                  // B fp16, 8 sub-slots x [128n][64k] = 128 KB, loaded ONCE
#define OFF_A0     131072             // A fp16 chunk (K=128): 2 sub-slots x 16 KB
#define OFF_A1     163840             // ends 196608
#define OFF_SWA    196608             // rowgroup aggregates: [8][128] f32 = 4 KB
#define OFF_SPRE   200704             // tile prefix 128 f32
#define OFF_STATE  201216             // lookback window state (int)
#define SMEM_TOTAL 201232

// device globals (no runtime allocation allowed)
__device__ __half g_Wh[G_DIM * L_DIM];          // W1^T as fp16, [n][k] k-major
__device__ float  g_aggregate[NUM_TILES * G_DIM];
__device__ float  g_inclusive[NUM_TILES * G_DIM];
__device__ int    g_flags[NUM_TILES];

#define SW128(o) ((o) ^ (((o) >> 3) & 0x70))

// ---- PTX helpers ----
__device__ __forceinline__ uint32_t smem_u32(const void* p) {
    uint32_t a;
    asm("{ .reg .u64 t; cvta.to.shared.u64 t, %1; cvt.u32.u64 %0, t; }" : "=r"(a) : "l"(p));
    return a;
}
__device__ __forceinline__ void ldsm_x4(uint32_t& r0, uint32_t& r1, uint32_t& r2,
                                        uint32_t& r3, uint32_t addr) {
    asm volatile("ldmatrix.sync.aligned.m8n8.x4.shared.b16 {%0,%1,%2,%3}, [%4];"
                 : "=r"(r0), "=r"(r1), "=r"(r2), "=r"(r3) : "r"(addr));
}
__device__ __forceinline__ void mma_f16(float* c, const uint32_t* a, uint32_t b0, uint32_t b1) {
    asm volatile(
        "mma.sync.aligned.m16n8k16.row.col.f32.f16.f16.f32 "
        "{%0,%1,%2,%3}, {%4,%5,%6,%7}, {%8,%9}, {%0,%1,%2,%3};"
        : "+f"(c[0]), "+f"(c[1]), "+f"(c[2]), "+f"(c[3])
        : "r"(a[0]), "r"(a[1]), "r"(a[2]), "r"(a[3]), "r"(b0), "r"(b1));
}
__device__ __forceinline__ void cp_async16(uint32_t dst, const void* src) {
    asm volatile("cp.async.cg.shared.global [%0], [%1], 16;" :: "r"(dst), "l"(src));
}
#define CP_COMMIT() asm volatile("cp.async.commit_group;" ::: "memory")
#define CP_WAIT0()  asm volatile("cp.async.wait_group 0;" ::: "memory")

__device__ __forceinline__ int ld_flag_cg(const int* p) {
    int f; asm volatile("ld.global.cg.b32 %0, [%1];" : "=r"(f) : "l"(p)); return f;
}
__device__ __forceinline__ float ld_f_cg(const float* p) {
    float f; asm volatile("ld.global.cg.f32 %0, [%1];" : "=f"(f) : "l"(p)); return f;
}
__device__ __forceinline__ void st_cs2(float* p, float a, float b) {
    asm volatile("st.global.cs.v2.f32 [%0], {%1,%2};" :: "l"(p), "f"(a), "f"(b) : "memory");
}

// ---- merged prep kernel (1 launch): W1 -> fp16 transpose, zero flags ----
__global__ void prep_kernel(const float* __restrict__ W1) {   // W1: [512][128]
    int idx = blockIdx.x * 256 + threadIdx.x;                 // 65536
    int k = idx >> 7, n = idx & 127;
    g_Wh[n * L_DIM + k] = __float2half_rn(W1[idx]);
    if (idx < NUM_TILES) g_flags[idx] = 0;
}

// ---- persistent fused kernel: HMMA GEMM + in-register cummax + lookback ----
__global__ void __launch_bounds__(NTHREADS, 1)
key_pool_mma(const float* __restrict__ A,      // [W, L]
             const float* __restrict__ gfeat,  // [G]
             const float* __restrict__ b1,     // [G]
             float* __restrict__ out, int write_tail) {
    extern __shared__ char sm[];
    const uint32_t smb = smem_u32(sm);
    float* Swa   = (float*)(sm + OFF_SWA);
    float* Spre  = (float*)(sm + OFF_SPRE);
    int*   Sstat = (int*)(sm + OFF_STATE);

    const int tid  = threadIdx.x;
    const int wid  = tid >> 5;
    const int lane = tid & 31;

    const int Rw = (wid & 7) * 16;   // warp row base (0..112)
    const int Cw = (wid >> 3) * 64;  // warp col base (0 or 64)
    const int rg = wid & 7;          // rowgroup index
    const int g  = lane >> 2;        // 0..7
    const int cq = (lane & 3) * 2;

    const __half* Wh = g_Wh;

    // ---- one-time prologue: all of B (128 KB) via cp.async ----
    #pragma unroll
    for (int i = 0; i < 16; ++i) {
        int e = tid + i * NTHREADS;              // 0..8191 uint4
        int slot = e >> 10, w = e & 1023;
        int n = w >> 3, u = w & 7;
        cp_async16(smb + OFF_B + slot * 16384 + SW128((uint32_t)(n * 128 + u * 16)),
                   Wh + n * L_DIM + slot * 64 + u * 8);
    }
    CP_COMMIT();

    // bias fragment (constant across tiles)
    float2 bc[8];
    #pragma unroll
    for (int nt = 0; nt < 8; ++nt)
        bc[nt] = *(const float2*)&b1[Cw + nt * 8 + cq];

    // ldmatrix per-thread offsets
    const int a_row  = (lane & 15);
    const int a_kb   = (lane >> 4) << 4;
    const int b_nrow = ((lane >> 4) & 1) * 8 + (lane & 7);
    const int b_kb   = ((lane >> 3) & 1) << 4;

    // A chunk-0 of first tile
    float4 ra[8];
    {
        const float4* A4 = (const float4*)(A + (size_t)blockIdx.x * TILE_ROWS * L_DIM);
        #pragma unroll
        for (int i = 0; i < 8; ++i) {
            int e = tid + i * NTHREADS, r = e >> 5, q = e & 31;
            ra[i] = __ldg(&A4[r * 128 + q]);
        }
    }
    CP_WAIT0();
    __syncthreads();   // B resident

    // ================= persistent tile loop =================
    for (int tile = blockIdx.x; tile < NUM_TILES; tile += NUM_CTAS) {
        const float4* A4 = (const float4*)(A + (size_t)tile * TILE_ROWS * L_DIM);

        float acc[8][4];
        #pragma unroll
        for (int nt = 0; nt < 8; ++nt) {   // init with bias: proj = A*W + b
            acc[nt][0] = bc[nt].x; acc[nt][1] = bc[nt].y;
            acc[nt][2] = bc[nt].x; acc[nt][3] = bc[nt].y;
        }

        // ---- mainloop: 4 chunks of K=128, one barrier each ----
        #pragma unroll
        for (int kc = 0; kc < NKCH; ++kc) {
            char* ahp = sm + ((kc & 1) ? OFF_A1 : OFF_A0);
            const uint32_t ahb = smb + ((kc & 1) ? OFF_A1 : OFF_A0);

            // convert + STS A(kc) from regs (loaded one phase ago)
            #pragma unroll
            for (int i = 0; i < 8; ++i) {
                int e = tid + i * NTHREADS, r = e >> 5, q = e & 31;
                __half2 h01 = __float22half2_rn(make_float2(ra[i].x, ra[i].y));
                __half2 h23 = __float22half2_rn(make_float2(ra[i].z, ra[i].w));
                *(uint2*)(ahp + (q >> 4) * 16384 + SW128((uint32_t)(r * 128 + (q & 15) * 8))) =
                    make_uint2(*(uint32_t*)&h01, *(uint32_t*)&h23);
            }
            // prefetch A(kc+1), or next tile's chunk 0 at kc==3
            if (kc < NKCH - 1) {
                #pragma unroll
                for (int i = 0; i < 8; ++i) {
                    int e = tid + i * NTHREADS, r = e >> 5, q = e & 31;
                    ra[i] = __ldg(&A4[r * 128 + (kc + 1) * 32 + q]);
                }
            } else if (tile + NUM_CTAS < NUM_TILES) {
                const float4* A4n =
                    (const float4*)(A + (size_t)(tile + NUM_CTAS) * TILE_ROWS * L_DIM);
                #pragma unroll
                for (int i = 0; i < 8; ++i) {
                    int e = tid + i * NTHREADS, r = e >> 5, q = e & 31;
                    ra[i] = __ldg(&A4n[r * 128 + q]);
                }
            }
            __syncthreads();   // A(kc) staged; prior-phase smem reads complete

            // ---- 8 k16 steps ----
            #pragma unroll
            for (int j = 0; j < 8; ++j) {
                uint32_t ah[4];
                {
                    uint32_t offA = (uint32_t)((Rw + a_row) * 128 + (j & 3) * 32 + a_kb);
                    ldsm_x4(ah[0], ah[1], ah[2], ah[3],
                            ahb + (j >> 2) * 16384 + SW128(offA));
                }
                const uint32_t bbb = smb + OFF_B + (kc * 2 + (j >> 2)) * 16384;
                const int kstep = (j & 3) * 32;
                #pragma unroll
                for (int nt2 = 0; nt2 < 4; ++nt2) {
                    uint32_t offB = (uint32_t)((Cw + nt2 * 16 + b_nrow) * 128 + kstep + b_kb);
                    uint32_t bf[4];
                    ldsm_x4(bf[0], bf[1], bf[2], bf[3], bbb + SW128(offB));
                    mma_f16(acc[nt2 * 2 + 0], ah, bf[0], bf[1]);
                    mma_f16(acc[nt2 * 2 + 1], ah, bf[2], bf[3]);
                }
            }
            __syncthreads();   // MMA(kc) reads done before next STS overwrites slot
        }

        // ---- in-register column cummax over the warp's 16 rows ----
        // thread holds rows (Rw+g, Rw+8+g), cols (cq, cq+1) per nt
        #pragma unroll
        for (int nt = 0; nt < 8; ++nt) {
            float c0 = acc[nt][0], c1 = acc[nt][1], c2 = acc[nt][2], c3 = acc[nt][3];
            #pragma unroll
            for (int d = 1; d < 8; d <<= 1) {
                float t0 = __shfl_up_sync(0xffffffffu, c0, d * 4);
                float t1 = __shfl_up_sync(0xffffffffu, c1, d * 4);
                float t2 = __shfl_up_sync(0xffffffffu, c2, d * 4);
                float t3 = __shfl_up_sync(0xffffffffu, c3, d * 4);
                if (g >= d) {
                    c0 = fmaxf(c0, t0); c1 = fmaxf(c1, t1);
                    c2 = fmaxf(c2, t2); c3 = fmaxf(c3, t3);
                }
            }
            // rows g+8 also cover rows Rw..Rw+7: fold in c0/c1 aggregate (g=7)
            float f0 = __shfl_sync(0xffffffffu, c0, 28 + (lane & 3));
            float f1 = __shfl_sync(0xffffffffu, c1, 28 + (lane & 3));
            c2 = fmaxf(c2, f0); c3 = fmaxf(c3, f1);
            acc[nt][0] = c0; acc[nt][1] = c1; acc[nt][2] = c2; acc[nt][3] = c3;
            // rowgroup aggregate (rows Rw..Rw+15) from g=7 lanes
            if (g == 7)
                *(float2*)&Swa[rg * G_DIM + Cw + nt * 8 + cq] = make_float2(c2, c3);
        }
        __syncthreads();

        // apply earlier-rowgroup prefixes from Swa
        #pragma unroll
        for (int nt = 0; nt < 8; ++nt) {
            float p0 = -FLT_MAX, p1 = -FLT_MAX;
            for (int q = 0; q < rg; ++q) {
                float2 w = *(float2*)&Swa[q * G_DIM + Cw + nt * 8 + cq];
                p0 = fmaxf(p0, w.x); p1 = fmaxf(p1, w.y);
            }
            acc[nt][0] = fmaxf(acc[nt][0], p0); acc[nt][1] = fmaxf(acc[nt][1], p1);
            acc[nt][2] = fmaxf(acc[nt][2], p0); acc[nt][3] = fmaxf(acc[nt][3], p1);
        }

        // tile column aggregate (all 8 rowgroups) for the scan state
        float tot = -FLT_MAX;
        if (tid < G_DIM) {
            #pragma unroll
            for (int q = 0; q < 8; ++q) tot = fmaxf(tot, Swa[q * G_DIM + tid]);
        }

        // ---- decoupled lookback (32-wide window) ----
        float incl = -FLT_MAX;
        if (tile == 0) {
            if (tid < G_DIM) {
                float run = __ldg(&gfeat[tid]);   // global-feature seed
                incl = fmaxf(tot, run);
                g_inclusive[tid] = incl;
                Spre[tid] = run;
            }
            __threadfence();
            __syncthreads();
            if (tid == 0) atomicExch(&g_flags[0], 2);
        } else {
            if (tid < G_DIM) g_aggregate[(size_t)tile * G_DIM + tid] = tot;
            __threadfence();
            __syncthreads();
            if (tid == 0) atomicExch(&g_flags[tile], 1);

            float run = -FLT_MAX;
            int p = tile - 1;
            while (true) {
                if (wid == 0) {
                    int idx = p - lane;
                    int f = 1;
                    if (idx >= 0) {
                        f = ld_flag_cg(&g_flags[idx]);
                        while (f == 0) { __nanosleep(32); f = ld_flag_cg(&g_flags[idx]); }
                    }
                    unsigned ball = __ballot_sync(0xffffffffu, f == 2);
                    if (lane == 0)
                        Sstat[0] = (ball == 0) ? 32 : (__ffs(ball) - 1);
                }
                __syncthreads();
                int l2 = Sstat[0];
                int lstop = (l2 < 32) ? l2 : 31;
                if (tid < G_DIM) {
                    for (int l = 0; l <= lstop; ++l) {
                        int idx = p - l;
                        const float* src = (l == l2) ? &g_inclusive[(size_t)idx * G_DIM]
                                                     : &g_aggregate[(size_t)idx * G_DIM];
                        run = fmaxf(run, ld_f_cg(&src[tid]));
                    }
                }
                __syncthreads();
                if (l2 < 32) break;
                p -= 32;
            }
            if (tid < G_DIM) {
                incl = fmaxf(run, tot);
                g_inclusive[(size_t)tile * G_DIM + tid] = incl;
                Spre[tid] = run;
            }
            __threadfence();
            __syncthreads();
            if (tid == 0) atomicExch(&g_flags[tile], 2);
        }
        __syncthreads();

        // ---- combine with tile prefix, store straight from registers ----
        float* outp = out + (size_t)tile * TILE_ROWS * G_DIM;
        #pragma unroll
        for (int nt = 0; nt < 8; ++nt) {
            int col = Cw + nt * 8 + cq;
            float2 pp = *(float2*)&Spre[col];
            int r0 = Rw + g;
            st_cs2(&outp[r0 * G_DIM + col],
                   fmaxf(acc[nt][0], pp.x), fmaxf(acc[nt][1], pp.y));
            st_cs2(&outp[(r0 + 8) * G_DIM + col],
                   fmaxf(acc[nt][2], pp.x), fmaxf(acc[nt][3], pp.y));
        }
        if (write_tail && tile == NUM_TILES - 1 && tid < G_DIM)
            out[(size_t)W_TOTAL * G_DIM + tid] = incl;

        __syncthreads();   // Spre/Swa safe to reuse next tile
    }
}

extern "C" void kernel_launch(void* const* d_in, const int* in_sizes, int n_in,
                              void* d_out, int out_size) {
    const float* local = (const float*)d_in[0];  // [262144, 512]
    const float* gfeat = (const float*)d_in[1];  // [1, 128]
    const float* W1    = (const float*)d_in[2];  // [512, 128]
    const float* b1    = (const float*)d_in[3];  // [128]
    float* out = (float*)d_out;

    static int configured = 0;
    if (!configured) {
        cudaFuncSetAttribute(key_pool_mma,
                             cudaFuncAttributeMaxDynamicSharedMemorySize, SMEM_TOTAL);
        configured = 1;
    }
    int write_tail = (out_size >= W_TOTAL * G_DIM + G_DIM) ? 1 : 0;

    prep_kernel<<<256, 256>>>(W1);
    key_pool_mma<<<NUM_CTAS, NTHREADS, SMEM_TOTAL>>>(local, gfeat, b1, out, write_tail);
}

// round 13
// speedup vs baseline: 1.2063x; 1.2063x over previous
#include <cuda_runtime.h>
#include <cuda_fp16.h>
#include <cstdint>
#include <cfloat>

#define W_TOTAL   262144
#define L_DIM     512
#define G_DIM     128
#define TILE_ROWS 256
#define NUM_TILES (W_TOTAL / TILE_ROWS)   // 1024
#define NKCH      8                       // K chunks of 64
#define NTHREADS  512

// ---- smem layout (bytes), dynamic smem only ----
#define OFF_B      0                  // B fp16, 8 sub-slots x [128n][64k] = 128 KB
#define OFF_A0     131072             // A fp16 chunk [256][64] = 32 KB
#define OFF_A1     163840             // ends 196608
#define OFF_SSC    131072             // epilogue reuse of A region: float[128][132] = 67584
#define SSC_PITCH  132
#define OFF_SB     198656             // bias 128 f32
#define OFF_SWA    199168             // warp aggregates [8][128] f32 = 4 KB
#define OFF_SPRE   203264             // tile prefix 128 f32
#define OFF_STATE  203776             // lookback state (int)
#define SMEM_TOTAL 203792

// device globals (no runtime allocation allowed)
__device__ __half g_Wh[G_DIM * L_DIM];          // W1^T fp16, [n][k] k-major
__device__ float  g_aggregate[NUM_TILES * G_DIM];
__device__ float  g_inclusive[NUM_TILES * G_DIM];
__device__ int    g_flags[NUM_TILES];

#define SW128(o) ((o) ^ (((o) >> 3) & 0x70))

// ---- PTX helpers ----
__device__ __forceinline__ uint32_t smem_u32(const void* p) {
    uint32_t a;
    asm("{ .reg .u64 t; cvta.to.shared.u64 t, %1; cvt.u32.u64 %0, t; }" : "=r"(a) : "l"(p));
    return a;
}
__device__ __forceinline__ void ldsm_x4(uint32_t& r0, uint32_t& r1, uint32_t& r2,
                                        uint32_t& r3, uint32_t addr) {
    asm volatile("ldmatrix.sync.aligned.m8n8.x4.shared.b16 {%0,%1,%2,%3}, [%4];"
                 : "=r"(r0), "=r"(r1), "=r"(r2), "=r"(r3) : "r"(addr));
}
__device__ __forceinline__ void mma_f16(float* c, const uint32_t* a, uint32_t b0, uint32_t b1) {
    asm volatile(
        "mma.sync.aligned.m16n8k16.row.col.f32.f16.f16.f32 "
        "{%0,%1,%2,%3}, {%4,%5,%6,%7}, {%8,%9}, {%0,%1,%2,%3};"
        : "+f"(c[0]), "+f"(c[1]), "+f"(c[2]), "+f"(c[3])
        : "r"(a[0]), "r"(a[1]), "r"(a[2]), "r"(a[3]), "r"(b0), "r"(b1));
}
__device__ __forceinline__ void cp_async16(uint32_t dst, const void* src) {
    asm volatile("cp.async.cg.shared.global [%0], [%1], 16;" :: "r"(dst), "l"(src));
}
#define CP_COMMIT() asm volatile("cp.async.commit_group;" ::: "memory")
#define CP_WAIT0()  asm volatile("cp.async.wait_group 0;" ::: "memory")

__device__ __forceinline__ int ld_flag_cg(const int* p) {
    int f; asm volatile("ld.global.cg.b32 %0, [%1];" : "=r"(f) : "l"(p)); return f;
}
__device__ __forceinline__ float ld_f_cg(const float* p) {
    float f; asm volatile("ld.global.cg.f32 %0, [%1];" : "=f"(f) : "l"(p)); return f;
}
__device__ __forceinline__ void st_cs4(float* p, float4 v) {
    asm volatile("st.global.cs.v4.f32 [%0], {%1,%2,%3,%4};"
                 :: "l"(p), "f"(v.x), "f"(v.y), "f"(v.z), "f"(v.w) : "memory");
}

// ---- merged prep kernel: W1 -> fp16 transpose, zero flags ----
__global__ void prep_kernel(const float* __restrict__ W1) {   // W1: [512][128]
    int idx = blockIdx.x * 256 + threadIdx.x;                 // 65536
    int k = idx >> 7, n = idx & 127;
    g_Wh[n * L_DIM + k] = __float2half_rn(W1[idx]);
    if (idx < NUM_TILES) g_flags[idx] = 0;
}

// ---- main fused kernel: 256-row tile HMMA GEMM + in-register cummax + lookback ----
__global__ void __launch_bounds__(NTHREADS, 1)
key_pool_mma(const float* __restrict__ A,      // [W, L]
             const float* __restrict__ gfeat,  // [G]
             const float* __restrict__ b1,     // [G]
             float* __restrict__ out, int write_tail) {
    extern __shared__ char sm[];
    const uint32_t smb = smem_u32(sm);
    float* Ssc   = (float*)(sm + OFF_SSC);
    float* Sb    = (float*)(sm + OFF_SB);
    float* Swa   = (float*)(sm + OFF_SWA);
    float* Spre  = (float*)(sm + OFF_SPRE);
    int*   Sstat = (int*)(sm + OFF_STATE);

    const int tid  = threadIdx.x;
    const int wid  = tid >> 5;
    const int lane = tid & 31;
    const int tile = blockIdx.x;

    const int rg = wid & 7;          // rowgroup 0..7 (32 rows each)
    const int Rw = rg * 32;          // warp row base
    const int Cw = (wid >> 3) * 64;  // warp col base (0 or 64)
    const int g  = lane >> 2;        // 0..7
    const int cq = (lane & 3) * 2;
    const int l4 = lane & 3;

    const float4* A4 = (const float4*)(A + (size_t)tile * TILE_ROWS * L_DIM);
    const __half* Wh = g_Wh;

    // ---- prologue: bias, all of B (128 KB), A chunk 0 ----
    if (tid < G_DIM) Sb[tid] = __ldg(&b1[tid]);
    #pragma unroll
    for (int i = 0; i < 16; ++i) {
        int e = tid + i * NTHREADS;              // 0..8191 uint4
        int slot = e >> 10, w = e & 1023;
        int n = w >> 3, u = w & 7;
        cp_async16(smb + OFF_B + slot * 16384 + SW128((uint32_t)(n * 128 + u * 16)),
                   Wh + n * L_DIM + slot * 64 + u * 8);
    }
    CP_COMMIT();

    float4 ra[8];                                // A chunk staging: 256 rows x 16 float4
    #pragma unroll
    for (int i = 0; i < 8; ++i) {
        int e = tid + i * NTHREADS, r = e >> 4, q = e & 15;
        ra[i] = __ldg(&A4[r * 128 + q]);
    }

    // ldmatrix per-thread offsets
    const int a_row  = (lane & 15);
    const int a_kb   = (lane >> 4) << 4;
    const int b_nrow = ((lane >> 4) & 1) * 8 + (lane & 7);
    const int b_kb   = ((lane >> 3) & 1) << 4;

    // accumulators (init with bias after prologue sync)
    float acc[2][8][4];

    CP_WAIT0();
    __syncthreads();   // B + bias resident

    #pragma unroll
    for (int t = 0; t < 2; ++t)
        #pragma unroll
        for (int nt = 0; nt < 8; ++nt) {
            float2 b2 = *(float2*)&Sb[Cw + nt * 8 + cq];
            acc[t][nt][0] = b2.x; acc[t][nt][1] = b2.y;
            acc[t][nt][2] = b2.x; acc[t][nt][3] = b2.y;
        }

    // ---- mainloop: 8 chunks of K=64, ONE barrier per chunk ----
    #pragma unroll
    for (int kc = 0; kc < NKCH; ++kc) {
        char* ahp = sm + ((kc & 1) ? OFF_A1 : OFF_A0);
        const uint32_t ahb = smb + ((kc & 1) ? OFF_A1 : OFF_A0);

        // convert + STS A(kc)
        #pragma unroll
        for (int i = 0; i < 8; ++i) {
            int e = tid + i * NTHREADS, r = e >> 4, q = e & 15;
            __half2 h01 = __float22half2_rn(make_float2(ra[i].x, ra[i].y));
            __half2 h23 = __float22half2_rn(make_float2(ra[i].z, ra[i].w));
            *(uint2*)(ahp + SW128((uint32_t)(r * 128 + q * 8))) =
                make_uint2(*(uint32_t*)&h01, *(uint32_t*)&h23);
        }
        // prefetch A(kc+1)
        if (kc < NKCH - 1) {
            #pragma unroll
            for (int i = 0; i < 8; ++i) {
                int e = tid + i * NTHREADS, r = e >> 4, q = e & 15;
                ra[i] = __ldg(&A4[r * 128 + (kc + 1) * 16 + q]);
            }
        }
        __syncthreads();   // A(kc) staged; prior chunk's LDSM reads complete

        const uint32_t bbb = smb + OFF_B + kc * 16384;
        #pragma unroll
        for (int j = 0; j < 4; ++j) {
            const int kstep = j * 32;
            uint32_t ah[2][4];
            #pragma unroll
            for (int t = 0; t < 2; ++t) {
                uint32_t offA = (uint32_t)((Rw + t * 16 + a_row) * 128 + kstep + a_kb);
                ldsm_x4(ah[t][0], ah[t][1], ah[t][2], ah[t][3], ahb + SW128(offA));
            }
            #pragma unroll
            for (int nt2 = 0; nt2 < 4; ++nt2) {
                uint32_t offB = (uint32_t)((Cw + nt2 * 16 + b_nrow) * 128 + kstep + b_kb);
                uint32_t bf[4];
                ldsm_x4(bf[0], bf[1], bf[2], bf[3], bbb + SW128(offB));
                #pragma unroll
                for (int half = 0; half < 2; ++half) {
                    const int nt = nt2 * 2 + half;
                    #pragma unroll
                    for (int t = 0; t < 2; ++t)
                        mma_f16(acc[t][nt], ah[t], bf[half * 2], bf[half * 2 + 1]);
                }
            }
        }
    }

    // ---- in-register column cummax over warp's 32 rows ----
    // t-group rows: t*16 + {g, 8+g}; cols per nt: Cw+nt*8+{cq,cq+1}
    #pragma unroll
    for (int nt = 0; nt < 8; ++nt) {
        #pragma unroll
        for (int t = 0; t < 2; ++t) {
            float c0 = acc[t][nt][0], c1 = acc[t][nt][1];
            float c2 = acc[t][nt][2], c3 = acc[t][nt][3];
            #pragma unroll
            for (int d = 1; d < 8; d <<= 1) {
                float t0 = __shfl_up_sync(0xffffffffu, c0, d * 4);
                float t1 = __shfl_up_sync(0xffffffffu, c1, d * 4);
                float t2 = __shfl_up_sync(0xffffffffu, c2, d * 4);
                float t3 = __shfl_up_sync(0xffffffffu, c3, d * 4);
                if (g >= d) {
                    c0 = fmaxf(c0, t0); c1 = fmaxf(c1, t1);
                    c2 = fmaxf(c2, t2); c3 = fmaxf(c3, t3);
                }
            }
            float f0 = __shfl_sync(0xffffffffu, c0, 28 + l4);
            float f1 = __shfl_sync(0xffffffffu, c1, 28 + l4);
            c2 = fmaxf(c2, f0); c3 = fmaxf(c3, f1);
            acc[t][nt][0] = c0; acc[t][nt][1] = c1;
            acc[t][nt][2] = c2; acc[t][nt][3] = c3;
        }
        // fold t=0 16-row total into t=1 (rows 16..31)
        float tt0 = __shfl_sync(0xffffffffu, acc[0][nt][2], 28 + l4);
        float tt1 = __shfl_sync(0xffffffffu, acc[0][nt][3], 28 + l4);
        acc[1][nt][0] = fmaxf(acc[1][nt][0], tt0);
        acc[1][nt][1] = fmaxf(acc[1][nt][1], tt1);
        acc[1][nt][2] = fmaxf(acc[1][nt][2], tt0);
        acc[1][nt][3] = fmaxf(acc[1][nt][3], tt1);
        // warp aggregate (32 rows) from g==7 lanes
        if (g == 7)
            *(float2*)&Swa[rg * G_DIM + Cw + nt * 8 + cq] =
                make_float2(acc[1][nt][2], acc[1][nt][3]);
    }
    __syncthreads();

    // ---- earlier-rowgroup prefixes ----
    #pragma unroll
    for (int nt = 0; nt < 8; ++nt) {
        float p0 = -FLT_MAX, p1 = -FLT_MAX;
        for (int q = 0; q < rg; ++q) {
            float2 w = *(float2*)&Swa[q * G_DIM + Cw + nt * 8 + cq];
            p0 = fmaxf(p0, w.x); p1 = fmaxf(p1, w.y);
        }
        #pragma unroll
        for (int t = 0; t < 2; ++t) {
            acc[t][nt][0] = fmaxf(acc[t][nt][0], p0);
            acc[t][nt][1] = fmaxf(acc[t][nt][1], p1);
            acc[t][nt][2] = fmaxf(acc[t][nt][2], p0);
            acc[t][nt][3] = fmaxf(acc[t][nt][3], p1);
        }
    }

    // tile column aggregate
    float tot = -FLT_MAX;
    if (tid < G_DIM) {
        #pragma unroll
        for (int q = 0; q < 8; ++q) tot = fmaxf(tot, Swa[q * G_DIM + tid]);
    }

    // ---- decoupled lookback (32-wide window), 1024 tiles ----
    float incl = -FLT_MAX;
    if (tile == 0) {
        if (tid < G_DIM) {
            float run = __ldg(&gfeat[tid]);       // global-feature seed
            incl = fmaxf(tot, run);
            g_inclusive[tid] = incl;
            Spre[tid] = run;
        }
        __threadfence();
        __syncthreads();
        if (tid == 0) atomicExch(&g_flags[0], 2);
    } else {
        if (tid < G_DIM) g_aggregate[(size_t)tile * G_DIM + tid] = tot;
        __threadfence();
        __syncthreads();
        if (tid == 0) atomicExch(&g_flags[tile], 1);

        float run = -FLT_MAX;
        int p = tile - 1;
        while (true) {
            if (wid == 0) {
                int idx = p - lane;
                int f = 1;
                if (idx >= 0) {
                    f = ld_flag_cg(&g_flags[idx]);
                    while (f == 0) { __nanosleep(32); f = ld_flag_cg(&g_flags[idx]); }
                }
                unsigned ball = __ballot_sync(0xffffffffu, f == 2);
                if (lane == 0)
                    Sstat[0] = (ball == 0) ? 32 : (__ffs(ball) - 1);
            }
            __syncthreads();
            int l2 = Sstat[0];
            int lstop = (l2 < 32) ? l2 : 31;
            if (tid < G_DIM) {
                for (int l = 0; l <= lstop; ++l) {
                    int idx = p - l;
                    const float* src = (l == l2) ? &g_inclusive[(size_t)idx * G_DIM]
                                                 : &g_aggregate[(size_t)idx * G_DIM];
                    run = fmaxf(run, ld_f_cg(&src[tid]));
                }
            }
            __syncthreads();
            if (l2 < 32) break;
            p -= 32;
        }
        if (tid < G_DIM) {
            incl = fmaxf(run, tot);
            g_inclusive[(size_t)tile * G_DIM + tid] = incl;
            Spre[tid] = run;
        }
        __threadfence();
        __syncthreads();
        if (tid == 0) atomicExch(&g_flags[tile], 2);
    }
    __syncthreads();

    // ---- staged stores: two 128-row passes through Ssc (A region reused) ----
    const int hw = rg >> 2;                       // which half this warp's rows are in
    #pragma unroll
    for (int h = 0; h < 2; ++h) {
        if (hw == h) {
            #pragma unroll
            for (int nt = 0; nt < 8; ++nt) {
                int col = Cw + nt * 8 + cq;
                float2 pp = *(float2*)&Spre[col];
                #pragma unroll
                for (int t = 0; t < 2; ++t) {
                    int r0 = Rw + t * 16 + g - h * 128;
                    *(float2*)&Ssc[r0 * SSC_PITCH + col] =
                        make_float2(fmaxf(acc[t][nt][0], pp.x), fmaxf(acc[t][nt][1], pp.y));
                    *(float2*)&Ssc[(r0 + 8) * SSC_PITCH + col] =
                        make_float2(fmaxf(acc[t][nt][2], pp.x), fmaxf(acc[t][nt][3], pp.y));
                }
            }
        }
        __syncthreads();
        float* outp = out + ((size_t)tile * TILE_ROWS + h * 128) * G_DIM;
        #pragma unroll
        for (int i = 0; i < 8; ++i) {
            int e = tid + i * NTHREADS;           // 0..4095 float4
            int r = e >> 5, c4 = e & 31;
            const float* s = &Ssc[r * SSC_PITCH + c4 * 4];
            st_cs4(&outp[e * 4], make_float4(s[0], s[1], s[2], s[3]));
        }
        __syncthreads();
    }
    if (write_tail && tile == NUM_TILES - 1 && tid < G_DIM)
        out[(size_t)W_TOTAL * G_DIM + tid] = incl;
}

extern "C" void kernel_launch(void* const* d_in, const int* in_sizes, int n_in,
                              void* d_out, int out_size) {
    const float* local = (const float*)d_in[0];  // [262144, 512]
    const float* gfeat = (const float*)d_in[1];  // [1, 128]
    const float* W1    = (const float*)d_in[2];  // [512, 128]
    const float* b1    = (const float*)d_in[3];  // [128]
    float* out = (float*)d_out;

    static int configured = 0;
    if (!configured) {
        cudaFuncSetAttribute(key_pool_mma,
                             cudaFuncAttributeMaxDynamicSharedMemorySize, SMEM_TOTAL);
        configured = 1;
    }
    int write_tail = (out_size >= W_TOTAL * G_DIM + G_DIM) ? 1 : 0;

    prep_kernel<<<256, 256>>>(W1);
    key_pool_mma<<<NUM_TILES, NTHREADS, SMEM_TOTAL>>>(local, gfeat, b1, out, write_tail);
}

// round 14
// speedup vs baseline: 1.2246x; 1.0151x over previous
#include <cuda_runtime.h>
#include <cuda_fp16.h>
#include <cstdint>
#include <cfloat>

#define W_TOTAL   262144
#define L_DIM     512
#define G_DIM     128
#define TILE_ROWS 128
#define NUM_TILES (W_TOTAL / TILE_ROWS)   // 2048
#define NKCH      8                       // K chunks of 64
#define NTHREADS  256

// ---- smem layout (bytes), dynamic smem only ----
#define OFF_A0     0                  // A fp16 [128][64], 16 KB
#define OFF_A1     16384
#define OFF_B0     32768              // B fp16 [128n][64k], 16 KB
#define OFF_B1     49152              // GEMM region ends 65536
#define OFF_SSC    0                  // epilogue reuse: float[128][132] = 67584
#define SSC_PITCH  132
#define OFF_SWA    67584              // rowgroup aggregates [4][128] f32 = 2 KB
#define OFF_SPRE   69632              // tile prefix 128 f32
#define OFF_STATE  70144              // lookback state (int)
#define SMEM_TOTAL 70160

// device globals (no runtime allocation allowed)
__device__ __half g_Wh[G_DIM * L_DIM];          // W1^T fp16, [n][k] k-major
__device__ float  g_aggregate[NUM_TILES * G_DIM];
__device__ float  g_inclusive[NUM_TILES * G_DIM];
__device__ int    g_flags[NUM_TILES];

#define SW128(o) ((o) ^ (((o) >> 3) & 0x70))

// ---- PTX helpers ----
__device__ __forceinline__ uint32_t smem_u32(const void* p) {
    uint32_t a;
    asm("{ .reg .u64 t; cvta.to.shared.u64 t, %1; cvt.u32.u64 %0, t; }" : "=r"(a) : "l"(p));
    return a;
}
__device__ __forceinline__ void ldsm_x4(uint32_t& r0, uint32_t& r1, uint32_t& r2,
                                        uint32_t& r3, uint32_t addr) {
    asm volatile("ldmatrix.sync.aligned.m8n8.x4.shared.b16 {%0,%1,%2,%3}, [%4];"
                 : "=r"(r0), "=r"(r1), "=r"(r2), "=r"(r3) : "r"(addr));
}
__device__ __forceinline__ void mma_f16(float* c, const uint32_t* a, uint32_t b0, uint32_t b1) {
    asm volatile(
        "mma.sync.aligned.m16n8k16.row.col.f32.f16.f16.f32 "
        "{%0,%1,%2,%3}, {%4,%5,%6,%7}, {%8,%9}, {%0,%1,%2,%3};"
        : "+f"(c[0]), "+f"(c[1]), "+f"(c[2]), "+f"(c[3])
        : "r"(a[0]), "r"(a[1]), "r"(a[2]), "r"(a[3]), "r"(b0), "r"(b1));
}
__device__ __forceinline__ void cp_async16(uint32_t dst, const void* src) {
    asm volatile("cp.async.cg.shared.global [%0], [%1], 16;" :: "r"(dst), "l"(src));
}
#define CP_COMMIT() asm volatile("cp.async.commit_group;" ::: "memory")
#define CP_WAIT0()  asm volatile("cp.async.wait_group 0;" ::: "memory")

__device__ __forceinline__ int ld_flag_cg(const int* p) {
    int f; asm volatile("ld.global.cg.b32 %0, [%1];" : "=r"(f) : "l"(p)); return f;
}
__device__ __forceinline__ float ld_f_cg(const float* p) {
    float f; asm volatile("ld.global.cg.f32 %0, [%1];" : "=f"(f) : "l"(p)); return f;
}
__device__ __forceinline__ void st_cs4(float* p, float4 v) {
    asm volatile("st.global.cs.v4.f32 [%0], {%1,%2,%3,%4};"
                 :: "l"(p), "f"(v.x), "f"(v.y), "f"(v.z), "f"(v.w) : "memory");
}

// ---- merged prep kernel: W1 -> fp16 transpose, zero flags ----
__global__ void prep_kernel(const float* __restrict__ W1) {   // W1: [512][128]
    int idx = blockIdx.x * 256 + threadIdx.x;                 // 65536
    int k = idx >> 7, n = idx & 127;
    g_Wh[n * L_DIM + k] = __float2half_rn(W1[idx]);
    if (idx < NUM_TILES) g_flags[idx] = 0;
}

// ---- main fused kernel: 2-CTA/SM, 32x64 warp-tile HMMA + in-register cummax ----
__global__ void __launch_bounds__(NTHREADS, 2)
key_pool_mma(const float* __restrict__ A,      // [W, L]
             const float* __restrict__ gfeat,  // [G]
             const float* __restrict__ b1,     // [G]
             float* __restrict__ out, int write_tail) {
    extern __shared__ char sm[];
    const uint32_t smb = smem_u32(sm);
    float* Ssc   = (float*)(sm + OFF_SSC);
    float* Swa   = (float*)(sm + OFF_SWA);
    float* Spre  = (float*)(sm + OFF_SPRE);
    int*   Sstat = (int*)(sm + OFF_STATE);

    const int tid  = threadIdx.x;
    const int wid  = tid >> 5;
    const int lane = tid & 31;
    const int tile = blockIdx.x;

    const int rg = wid & 3;          // rowgroup 0..3 (32 rows each)
    const int Rw = rg * 32;          // warp row base
    const int Cw = (wid >> 2) * 64;  // warp col base (0 or 64)
    const int g  = lane >> 2;        // 0..7
    const int cq = (lane & 3) * 2;
    const int l4 = lane & 3;

    const float4* A4 = (const float4*)(A + (size_t)tile * TILE_ROWS * L_DIM);
    const __half* Wh = g_Wh;

    // ---- prologue: LDG A(0) into regs, cp.async B(0), bias into regs ----
    float4 ra[8];
    #pragma unroll
    for (int i = 0; i < 8; ++i) {
        int e = tid + i * NTHREADS, r = e >> 4, q = e & 15;   // [128 rows][16 q]
        ra[i] = __ldg(&A4[r * 128 + q]);
    }
    #pragma unroll
    for (int i = 0; i < 4; ++i) {
        int e = tid + i * NTHREADS, n = e >> 3, u = e & 7;
        cp_async16(smb + OFF_B0 + SW128((uint32_t)(n * 128 + u * 16)),
                   Wh + n * L_DIM + u * 8);
    }
    CP_COMMIT();

    // accumulators init with bias: proj = A*W + b
    float acc[2][8][4];
    #pragma unroll
    for (int nt = 0; nt < 8; ++nt) {
        float2 b2 = *(const float2*)&b1[Cw + nt * 8 + cq];
        #pragma unroll
        for (int t = 0; t < 2; ++t) {
            acc[t][nt][0] = b2.x; acc[t][nt][1] = b2.y;
            acc[t][nt][2] = b2.x; acc[t][nt][3] = b2.y;
        }
    }

    // ldmatrix per-thread offsets
    const int a_row  = (lane & 15);
    const int a_kb   = (lane >> 4) << 4;
    const int b_nrow = ((lane >> 4) & 1) * 8 + (lane & 7);
    const int b_kb   = ((lane >> 3) & 1) << 4;

    // ---- pipelined mainloop: one __syncthreads per chunk (R6 scheme) ----
    #pragma unroll
    for (int kc = 0; kc < NKCH; ++kc) {
        char* ahp = sm + ((kc & 1) ? OFF_A1 : OFF_A0);
        const uint32_t ahb = smb + ((kc & 1) ? OFF_A1 : OFF_A0);
        const uint32_t bbb = smb + ((kc & 1) ? OFF_B1 : OFF_B0);

        // convert + STS A(kc)
        #pragma unroll
        for (int i = 0; i < 8; ++i) {
            int e = tid + i * NTHREADS, r = e >> 4, q = e & 15;
            __half2 h01 = __float22half2_rn(make_float2(ra[i].x, ra[i].y));
            __half2 h23 = __float22half2_rn(make_float2(ra[i].z, ra[i].w));
            *(uint2*)(ahp + SW128((uint32_t)(r * 128 + q * 8))) =
                make_uint2(*(uint32_t*)&h01, *(uint32_t*)&h23);
        }
        // prefetch A(kc+1)
        if (kc < NKCH - 1) {
            #pragma unroll
            for (int i = 0; i < 8; ++i) {
                int e = tid + i * NTHREADS, r = e >> 4, q = e & 15;
                ra[i] = __ldg(&A4[r * 128 + (kc + 1) * 16 + q]);
            }
        }

        CP_WAIT0();          // B(kc) landed
        __syncthreads();     // all staged; MMA(kc-1) complete

        // cp.async B(kc+1) into the other buffer (safe: MMA(kc-1) done)
        if (kc < NKCH - 1) {
            const uint32_t bnext = smb + (((kc + 1) & 1) ? OFF_B1 : OFF_B0);
            #pragma unroll
            for (int i = 0; i < 4; ++i) {
                int e = tid + i * NTHREADS, n = e >> 3, u = e & 7;
                cp_async16(bnext + SW128((uint32_t)(n * 128 + u * 16)),
                           Wh + n * L_DIM + (kc + 1) * 64 + u * 8);
            }
            CP_COMMIT();
        }

        // ---- MMA over 4 k16 steps (warp tile 32x64) ----
        #pragma unroll
        for (int j = 0; j < 4; ++j) {
            const int kstep = j * 32;
            uint32_t ah[2][4];
            #pragma unroll
            for (int t = 0; t < 2; ++t) {
                uint32_t offA = (uint32_t)((Rw + t * 16 + a_row) * 128 + kstep + a_kb);
                ldsm_x4(ah[t][0], ah[t][1], ah[t][2], ah[t][3], ahb + SW128(offA));
            }
            #pragma unroll
            for (int nt2 = 0; nt2 < 4; ++nt2) {
                uint32_t offB = (uint32_t)((Cw + nt2 * 16 + b_nrow) * 128 + kstep + b_kb);
                uint32_t bf[4];
                ldsm_x4(bf[0], bf[1], bf[2], bf[3], bbb + SW128(offB));
                #pragma unroll
                for (int half = 0; half < 2; ++half) {
                    const int nt = nt2 * 2 + half;
                    #pragma unroll
                    for (int t = 0; t < 2; ++t)
                        mma_f16(acc[t][nt], ah[t], bf[half * 2], bf[half * 2 + 1]);
                }
            }
        }
    }

    // ---- in-register column cummax over warp's 32 rows (R13-proven) ----
    #pragma unroll
    for (int nt = 0; nt < 8; ++nt) {
        #pragma unroll
        for (int t = 0; t < 2; ++t) {
            float c0 = acc[t][nt][0], c1 = acc[t][nt][1];
            float c2 = acc[t][nt][2], c3 = acc[t][nt][3];
            #pragma unroll
            for (int d = 1; d < 8; d <<= 1) {
                float t0 = __shfl_up_sync(0xffffffffu, c0, d * 4);
                float t1 = __shfl_up_sync(0xffffffffu, c1, d * 4);
                float t2 = __shfl_up_sync(0xffffffffu, c2, d * 4);
                float t3 = __shfl_up_sync(0xffffffffu, c3, d * 4);
                if (g >= d) {
                    c0 = fmaxf(c0, t0); c1 = fmaxf(c1, t1);
                    c2 = fmaxf(c2, t2); c3 = fmaxf(c3, t3);
                }
            }
            float f0 = __shfl_sync(0xffffffffu, c0, 28 + l4);
            float f1 = __shfl_sync(0xffffffffu, c1, 28 + l4);
            c2 = fmaxf(c2, f0); c3 = fmaxf(c3, f1);
            acc[t][nt][0] = c0; acc[t][nt][1] = c1;
            acc[t][nt][2] = c2; acc[t][nt][3] = c3;
        }
        // fold t=0 16-row total into t=1 (rows 16..31)
        float tt0 = __shfl_sync(0xffffffffu, acc[0][nt][2], 28 + l4);
        float tt1 = __shfl_sync(0xffffffffu, acc[0][nt][3], 28 + l4);
        acc[1][nt][0] = fmaxf(acc[1][nt][0], tt0);
        acc[1][nt][1] = fmaxf(acc[1][nt][1], tt1);
        acc[1][nt][2] = fmaxf(acc[1][nt][2], tt0);
        acc[1][nt][3] = fmaxf(acc[1][nt][3], tt1);
        // warp aggregate (32 rows) from g==7 lanes
        if (g == 7)
            *(float2*)&Swa[rg * G_DIM + Cw + nt * 8 + cq] =
                make_float2(acc[1][nt][2], acc[1][nt][3]);
    }
    __syncthreads();   // also: all MMA/LDSM done before Ssc overwrites GEMM smem

    // ---- earlier-rowgroup prefixes ----
    #pragma unroll
    for (int nt = 0; nt < 8; ++nt) {
        float p0 = -FLT_MAX, p1 = -FLT_MAX;
        for (int q = 0; q < rg; ++q) {
            float2 w = *(float2*)&Swa[q * G_DIM + Cw + nt * 8 + cq];
            p0 = fmaxf(p0, w.x); p1 = fmaxf(p1, w.y);
        }
        #pragma unroll
        for (int t = 0; t < 2; ++t) {
            acc[t][nt][0] = fmaxf(acc[t][nt][0], p0);
            acc[t][nt][1] = fmaxf(acc[t][nt][1], p1);
            acc[t][nt][2] = fmaxf(acc[t][nt][2], p0);
            acc[t][nt][3] = fmaxf(acc[t][nt][3], p1);
        }
    }

    // tile column aggregate (4 rowgroups)
    float tot = -FLT_MAX;
    if (tid < G_DIM) {
        #pragma unroll
        for (int q = 0; q < 4; ++q) tot = fmaxf(tot, Swa[q * G_DIM + tid]);
    }

    // ---- decoupled lookback (32-wide window) ----
    float incl = -FLT_MAX;
    if (tile == 0) {
        if (tid < G_DIM) {
            float run = __ldg(&gfeat[tid]);       // global-feature seed
            incl = fmaxf(tot, run);
            g_inclusive[tid] = incl;
            Spre[tid] = run;
        }
        __threadfence();
        __syncthreads();
        if (tid == 0) atomicExch(&g_flags[0], 2);
    } else {
        if (tid < G_DIM) g_aggregate[(size_t)tile * G_DIM + tid] = tot;
        __threadfence();
        __syncthreads();
        if (tid == 0) atomicExch(&g_flags[tile], 1);

        float run = -FLT_MAX;
        int p = tile - 1;
        while (true) {
            if (wid == 0) {
                int idx = p - lane;
                int f = 1;
                if (idx >= 0) {
                    f = ld_flag_cg(&g_flags[idx]);
                    while (f == 0) { __nanosleep(32); f = ld_flag_cg(&g_flags[idx]); }
                }
                unsigned ball = __ballot_sync(0xffffffffu, f == 2);
                if (lane == 0)
                    Sstat[0] = (ball == 0) ? 32 : (__ffs(ball) - 1);
            }
            __syncthreads();
            int l2 = Sstat[0];
            int lstop = (l2 < 32) ? l2 : 31;
            if (tid < G_DIM) {
                for (int l = 0; l <= lstop; ++l) {
                    int idx = p - l;
                    const float* src = (l == l2) ? &g_inclusive[(size_t)idx * G_DIM]
                                                 : &g_aggregate[(size_t)idx * G_DIM];
                    run = fmaxf(run, ld_f_cg(&src[tid]));
                }
            }
            __syncthreads();
            if (l2 < 32) break;
            p -= 32;
        }
        if (tid < G_DIM) {
            incl = fmaxf(run, tot);
            g_inclusive[(size_t)tile * G_DIM + tid] = incl;
            Spre[tid] = run;
        }
        __threadfence();
        __syncthreads();
        if (tid == 0) atomicExch(&g_flags[tile], 2);
    }
    __syncthreads();

    // ---- combine with tile prefix into Ssc, then staged float4 stores ----
    #pragma unroll
    for (int nt = 0; nt < 8; ++nt) {
        int col = Cw + nt * 8 + cq;
        float2 pp = *(float2*)&Spre[col];
        #pragma unroll
        for (int t = 0; t < 2; ++t) {
            int r0 = Rw + t * 16 + g;
            *(float2*)&Ssc[r0 * SSC_PITCH + col] =
                make_float2(fmaxf(acc[t][nt][0], pp.x), fmaxf(acc[t][nt][1], pp.y));
            *(float2*)&Ssc[(r0 + 8) * SSC_PITCH + col] =
                make_float2(fmaxf(acc[t][nt][2], pp.x), fmaxf(acc[t][nt][3], pp.y));
        }
    }
    __syncthreads();

    float* outp = out + (size_t)tile * TILE_ROWS * G_DIM;
    #pragma unroll
    for (int i = 0; i < 16; ++i) {
        int e = tid + i * NTHREADS;               // 0..4095 float4
        int r = e >> 5, c4 = e & 31;
        const float* s = &Ssc[r * SSC_PITCH + c4 * 4];
        st_cs4(&outp[e * 4], make_float4(s[0], s[1], s[2], s[3]));
    }
    if (write_tail && tile == NUM_TILES - 1 && tid < G_DIM)
        out[(size_t)W_TOTAL * G_DIM + tid] = incl;
}

extern "C" void kernel_launch(void* const* d_in, const int* in_sizes, int n_in,
                              void* d_out, int out_size) {
    const float* local = (const float*)d_in[0];  // [262144, 512]
    const float* gfeat = (const float*)d_in[1];  // [1, 128]
    const float* W1    = (const float*)d_in[2];  // [512, 128]
    const float* b1    = (const float*)d_in[3];  // [128]
    float* out = (float*)d_out;

    static int configured = 0;
    if (!configured) {
        cudaFuncSetAttribute(key_pool_mma,
                             cudaFuncAttributeMaxDynamicSharedMemorySize, SMEM_TOTAL);
        configured = 1;
    }
    int write_tail = (out_size >= W_TOTAL * G_DIM + G_DIM) ? 1 : 0;

    prep_kernel<<<256, 256>>>(W1);
    key_pool_mma<<<NUM_TILES, NTHREADS, SMEM_TOTAL>>>(local, gfeat, b1, out, write_tail);
}

// round 15
// speedup vs baseline: 1.5063x; 1.2301x over previous
#include <cuda_runtime.h>
#include <cuda_fp16.h>
#include <cstdint>
#include <cfloat>

#define W_TOTAL   262144
#define L_DIM     512
#define G_DIM     128
#define TILE_ROWS 128
#define NUM_TILES (W_TOTAL / TILE_ROWS)   // 2048
#define NKCH      8                       // K chunks of 64
#define NTHREADS  256

// ---- smem layout (bytes), dynamic smem only ----
#define OFF_RAW0   0                  // raw fp32 A chunk [128][64] = 32 KB
#define OFF_RAW1   32768
#define OFF_AH     65536              // A fp16 [128][64], single buffer, 16 KB
#define OFF_B0     81920              // B fp16 [128n][64k], 16 KB
#define OFF_B1     98304              // GEMM region ends 114688
#define OFF_SSC    0                  // epilogue reuse: float[128][132] = 67584 (over RAW)
#define SSC_PITCH  132
#define OFF_SWA    67584              // rowgroup aggregates [4][128] f32 = 2 KB (in dead AH)
#define OFF_SPRE   69632              // tile prefix 128 f32
#define OFF_STATE  70144              // lookback state (int)
#define SMEM_TOTAL 114688

// device globals (no runtime allocation allowed)
__device__ __half g_Wh[G_DIM * L_DIM];          // W1^T fp16, [n][k] k-major
__device__ float  g_aggregate[NUM_TILES * G_DIM];
__device__ float  g_inclusive[NUM_TILES * G_DIM];
__device__ int    g_flags[NUM_TILES];

#define SW128(o) ((o) ^ (((o) >> 3) & 0x70))

// ---- PTX helpers ----
__device__ __forceinline__ uint32_t smem_u32(const void* p) {
    uint32_t a;
    asm("{ .reg .u64 t; cvta.to.shared.u64 t, %1; cvt.u32.u64 %0, t; }" : "=r"(a) : "l"(p));
    return a;
}
__device__ __forceinline__ void ldsm_x4(uint32_t& r0, uint32_t& r1, uint32_t& r2,
                                        uint32_t& r3, uint32_t addr) {
    asm volatile("ldmatrix.sync.aligned.m8n8.x4.shared.b16 {%0,%1,%2,%3}, [%4];"
                 : "=r"(r0), "=r"(r1), "=r"(r2), "=r"(r3) : "r"(addr));
}
__device__ __forceinline__ void mma_f16(float* c, const uint32_t* a, uint32_t b0, uint32_t b1) {
    asm volatile(
        "mma.sync.aligned.m16n8k16.row.col.f32.f16.f16.f32 "
        "{%0,%1,%2,%3}, {%4,%5,%6,%7}, {%8,%9}, {%0,%1,%2,%3};"
        : "+f"(c[0]), "+f"(c[1]), "+f"(c[2]), "+f"(c[3])
        : "r"(a[0]), "r"(a[1]), "r"(a[2]), "r"(a[3]), "r"(b0), "r"(b1));
}
__device__ __forceinline__ void cp_async16(uint32_t dst, const void* src) {
    asm volatile("cp.async.cg.shared.global [%0], [%1], 16;" :: "r"(dst), "l"(src));
}
#define CP_COMMIT() asm volatile("cp.async.commit_group;" ::: "memory")
#define CP_WAIT0()  asm volatile("cp.async.wait_group 0;" ::: "memory")

__device__ __forceinline__ int ld_flag_cg(const int* p) {
    int f; asm volatile("ld.global.cg.b32 %0, [%1];" : "=r"(f) : "l"(p)); return f;
}
__device__ __forceinline__ float ld_f_cg(const float* p) {
    float f; asm volatile("ld.global.cg.f32 %0, [%1];" : "=f"(f) : "l"(p)); return f;
}
__device__ __forceinline__ void st_cs4(float* p, float4 v) {
    asm volatile("st.global.cs.v4.f32 [%0], {%1,%2,%3,%4};"
                 :: "l"(p), "f"(v.x), "f"(v.y), "f"(v.z), "f"(v.w) : "memory");
}

// ---- merged prep kernel: W1 -> fp16 transpose, zero flags ----
__global__ void prep_kernel(const float* __restrict__ W1) {   // W1: [512][128]
    int idx = blockIdx.x * 256 + threadIdx.x;                 // 65536
    int k = idx >> 7, n = idx & 127;
    g_Wh[n * L_DIM + k] = __float2half_rn(W1[idx]);
    if (idx < NUM_TILES) g_flags[idx] = 0;
}

// ---- main fused kernel: spill-free 2-CTA/SM HMMA + in-register cummax ----
__global__ void __launch_bounds__(NTHREADS, 2)
key_pool_mma(const float* __restrict__ A,      // [W, L]
             const float* __restrict__ gfeat,  // [G]
             const float* __restrict__ b1,     // [G]
             float* __restrict__ out, int write_tail) {
    extern __shared__ char sm[];
    const uint32_t smb = smem_u32(sm);
    float* Ssc   = (float*)(sm + OFF_SSC);
    float* Swa   = (float*)(sm + OFF_SWA);
    float* Spre  = (float*)(sm + OFF_SPRE);
    int*   Sstat = (int*)(sm + OFF_STATE);

    const int tid  = threadIdx.x;
    const int wid  = tid >> 5;
    const int lane = tid & 31;
    const int tile = blockIdx.x;

    const int rg = wid & 3;          // rowgroup 0..3 (32 rows each)
    const int Rw = rg * 32;          // warp row base
    const int Cw = (wid >> 2) * 64;  // warp col base (0 or 64)
    const int g  = lane >> 2;        // 0..7
    const int cq = (lane & 3) * 2;
    const int l4 = lane & 3;

    const float4* A4 = (const float4*)(A + (size_t)tile * TILE_ROWS * L_DIM);
    const __half* Wh = g_Wh;

    // ---- prologue: cp.async raw A(0) fp32 + B(0) ----
    #pragma unroll
    for (int i = 0; i < 8; ++i) {
        int e = tid + i * NTHREADS;              // 0..2047 float4 (32 KB)
        int r = e >> 4, q = e & 15;
        cp_async16(smb + OFF_RAW0 + e * 16, &A4[r * 128 + q]);
    }
    #pragma unroll
    for (int i = 0; i < 4; ++i) {
        int e = tid + i * NTHREADS, n = e >> 3, u = e & 7;
        cp_async16(smb + OFF_B0 + SW128((uint32_t)(n * 128 + u * 16)),
                   Wh + n * L_DIM + u * 8);
    }
    CP_COMMIT();

    // accumulators init with bias: proj = A*W + b
    float acc[2][8][4];
    #pragma unroll
    for (int nt = 0; nt < 8; ++nt) {
        float2 b2 = *(const float2*)&b1[Cw + nt * 8 + cq];
        #pragma unroll
        for (int t = 0; t < 2; ++t) {
            acc[t][nt][0] = b2.x; acc[t][nt][1] = b2.y;
            acc[t][nt][2] = b2.x; acc[t][nt][3] = b2.y;
        }
    }

    // ldmatrix per-thread offsets
    const int a_row  = (lane & 15);
    const int a_kb   = (lane >> 4) << 4;
    const int b_nrow = ((lane >> 4) & 1) * 8 + (lane & 7);
    const int b_kb   = ((lane >> 3) & 1) << 4;
    const uint32_t ahb = smb + OFF_AH;

    // ---- mainloop: 8 chunks, 2 barriers each, zero A registers held ----
    #pragma unroll
    for (int kc = 0; kc < NKCH; ++kc) {
        char* rawp = sm + ((kc & 1) ? OFF_RAW1 : OFF_RAW0);
        const uint32_t bbb = smb + ((kc & 1) ? OFF_B1 : OFF_B0);

        CP_WAIT0();          // raw(kc) + B(kc) landed (self-issued elements)
        __syncthreads();     // barrier1: MMA(kc-1) reads of Ah/B(kc-1) complete

        // prefetch raw A(kc+1) + B(kc+1) (their buffers' readers finished pre-barrier1)
        if (kc < NKCH - 1) {
            char* rawn = sm + (((kc + 1) & 1) ? OFF_RAW1 : OFF_RAW0);
            const uint32_t rawnb = smb + (uint32_t)(rawn - sm);
            #pragma unroll
            for (int i = 0; i < 8; ++i) {
                int e = tid + i * NTHREADS, r = e >> 4, q = e & 15;
                cp_async16(rawnb + e * 16, &A4[r * 128 + (kc + 1) * 16 + q]);
            }
            const uint32_t bnext = smb + (((kc + 1) & 1) ? OFF_B1 : OFF_B0);
            #pragma unroll
            for (int i = 0; i < 4; ++i) {
                int e = tid + i * NTHREADS, n = e >> 3, u = e & 7;
                cp_async16(bnext + SW128((uint32_t)(n * 128 + u * 16)),
                           Wh + n * L_DIM + (kc + 1) * 64 + u * 8);
            }
            CP_COMMIT();
        }

        // convert raw(kc) fp32 -> Ah fp16 (smem -> smem, swizzled)
        #pragma unroll
        for (int i = 0; i < 8; ++i) {
            int e = tid + i * NTHREADS, r = e >> 4, q = e & 15;
            float4 v = *(const float4*)(rawp + e * 16);
            __half2 h01 = __float22half2_rn(make_float2(v.x, v.y));
            __half2 h23 = __float22half2_rn(make_float2(v.z, v.w));
            *(uint2*)(sm + OFF_AH + SW128((uint32_t)(r * 128 + q * 8))) =
                make_uint2(*(uint32_t*)&h01, *(uint32_t*)&h23);
        }
        __syncthreads();     // barrier2: Ah(kc) + B(kc) visible to all warps

        // ---- MMA over 4 k16 steps (warp tile 32x64) ----
        #pragma unroll
        for (int j = 0; j < 4; ++j) {
            const int kstep = j * 32;
            uint32_t ah[2][4];
            #pragma unroll
            for (int t = 0; t < 2; ++t) {
                uint32_t offA = (uint32_t)((Rw + t * 16 + a_row) * 128 + kstep + a_kb);
                ldsm_x4(ah[t][0], ah[t][1], ah[t][2], ah[t][3], ahb + SW128(offA));
            }
            #pragma unroll
            for (int nt2 = 0; nt2 < 4; ++nt2) {
                uint32_t offB = (uint32_t)((Cw + nt2 * 16 + b_nrow) * 128 + kstep + b_kb);
                uint32_t bf[4];
                ldsm_x4(bf[0], bf[1], bf[2], bf[3], bbb + SW128(offB));
                #pragma unroll
                for (int half = 0; half < 2; ++half) {
                    const int nt = nt2 * 2 + half;
                    #pragma unroll
                    for (int t = 0; t < 2; ++t)
                        mma_f16(acc[t][nt], ah[t], bf[half * 2], bf[half * 2 + 1]);
                }
            }
        }
    }

    // ---- in-register column cummax over warp's 32 rows ----
    #pragma unroll
    for (int nt = 0; nt < 8; ++nt) {
        #pragma unroll
        for (int t = 0; t < 2; ++t) {
            float c0 = acc[t][nt][0], c1 = acc[t][nt][1];
            float c2 = acc[t][nt][2], c3 = acc[t][nt][3];
            #pragma unroll
            for (int d = 1; d < 8; d <<= 1) {
                float t0 = __shfl_up_sync(0xffffffffu, c0, d * 4);
                float t1 = __shfl_up_sync(0xffffffffu, c1, d * 4);
                float t2 = __shfl_up_sync(0xffffffffu, c2, d * 4);
                float t3 = __shfl_up_sync(0xffffffffu, c3, d * 4);
                if (g >= d) {
                    c0 = fmaxf(c0, t0); c1 = fmaxf(c1, t1);
                    c2 = fmaxf(c2, t2); c3 = fmaxf(c3, t3);
                }
            }
            float f0 = __shfl_sync(0xffffffffu, c0, 28 + l4);
            float f1 = __shfl_sync(0xffffffffu, c1, 28 + l4);
            c2 = fmaxf(c2, f0); c3 = fmaxf(c3, f1);
            acc[t][nt][0] = c0; acc[t][nt][1] = c1;
            acc[t][nt][2] = c2; acc[t][nt][3] = c3;
        }
        // fold t=0 16-row total into t=1 (rows 16..31)
        float tt0 = __shfl_sync(0xffffffffu, acc[0][nt][2], 28 + l4);
        float tt1 = __shfl_sync(0xffffffffu, acc[0][nt][3], 28 + l4);
        acc[1][nt][0] = fmaxf(acc[1][nt][0], tt0);
        acc[1][nt][1] = fmaxf(acc[1][nt][1], tt1);
        acc[1][nt][2] = fmaxf(acc[1][nt][2], tt0);
        acc[1][nt][3] = fmaxf(acc[1][nt][3], tt1);
        if (g == 7)
            *(float2*)&Swa[rg * G_DIM + Cw + nt * 8 + cq] =
                make_float2(acc[1][nt][2], acc[1][nt][3]);
    }
    __syncthreads();   // all MMA/LDSM done before Ssc overwrites GEMM smem

    // ---- earlier-rowgroup prefixes ----
    #pragma unroll
    for (int nt = 0; nt < 8; ++nt) {
        float p0 = -FLT_MAX, p1 = -FLT_MAX;
        for (int q = 0; q < rg; ++q) {
            float2 w = *(float2*)&Swa[q * G_DIM + Cw + nt * 8 + cq];
            p0 = fmaxf(p0, w.x); p1 = fmaxf(p1, w.y);
        }
        #pragma unroll
        for (int t = 0; t < 2; ++t) {
            acc[t][nt][0] = fmaxf(acc[t][nt][0], p0);
            acc[t][nt][1] = fmaxf(acc[t][nt][1], p1);
            acc[t][nt][2] = fmaxf(acc[t][nt][2], p0);
            acc[t][nt][3] = fmaxf(acc[t][nt][3], p1);
        }
    }

    // tile column aggregate (4 rowgroups)
    float tot = -FLT_MAX;
    if (tid < G_DIM) {
        #pragma unroll
        for (int q = 0; q < 4; ++q) tot = fmaxf(tot, Swa[q * G_DIM + tid]);
    }

    // ---- decoupled lookback (32-wide window) ----
    float incl = -FLT_MAX;
    if (tile == 0) {
        if (tid < G_DIM) {
            float run = __ldg(&gfeat[tid]);       // global-feature seed
            incl = fmaxf(tot, run);
            g_inclusive[tid] = incl;
            Spre[tid] = run;
        }
        __threadfence();
        __syncthreads();
        if (tid == 0) atomicExch(&g_flags[0], 2);
    } else {
        if (tid < G_DIM) g_aggregate[(size_t)tile * G_DIM + tid] = tot;
        __threadfence();
        __syncthreads();
        if (tid == 0) atomicExch(&g_flags[tile], 1);

        float run = -FLT_MAX;
        int p = tile - 1;
        while (true) {
            if (wid == 0) {
                int idx = p - lane;
                int f = 1;
                if (idx >= 0) {
                    f = ld_flag_cg(&g_flags[idx]);
                    while (f == 0) { __nanosleep(32); f = ld_flag_cg(&g_flags[idx]); }
                }
                unsigned ball = __ballot_sync(0xffffffffu, f == 2);
                if (lane == 0)
                    Sstat[0] = (ball == 0) ? 32 : (__ffs(ball) - 1);
            }
            __syncthreads();
            int l2 = Sstat[0];
            int lstop = (l2 < 32) ? l2 : 31;
            if (tid < G_DIM) {
                for (int l = 0; l <= lstop; ++l) {
                    int idx = p - l;
                    const float* src = (l == l2) ? &g_inclusive[(size_t)idx * G_DIM]
                                                 : &g_aggregate[(size_t)idx * G_DIM];
                    run = fmaxf(run, ld_f_cg(&src[tid]));
                }
            }
            __syncthreads();
            if (l2 < 32) break;
            p -= 32;
        }
        if (tid < G_DIM) {
            incl = fmaxf(run, tot);
            g_inclusive[(size_t)tile * G_DIM + tid] = incl;
            Spre[tid] = run;
        }
        __threadfence();
        __syncthreads();
        if (tid == 0) atomicExch(&g_flags[tile], 2);
    }
    __syncthreads();

    // ---- combine with tile prefix into Ssc, then staged float4 stores ----
    #pragma unroll
    for (int nt = 0; nt < 8; ++nt) {
        int col = Cw + nt * 8 + cq;
        float2 pp = *(float2*)&Spre[col];
        #pragma unroll
        for (int t = 0; t < 2; ++t) {
            int r0 = Rw + t * 16 + g;
            *(float2*)&Ssc[r0 * SSC_PITCH + col] =
                make_float2(fmaxf(acc[t][nt][0], pp.x), fmaxf(acc[t][nt][1], pp.y));
            *(float2*)&Ssc[(r0 + 8) * SSC_PITCH + col] =
                make_float2(fmaxf(acc[t][nt][2], pp.x), fmaxf(acc[t][nt][3], pp.y));
        }
    }
    __syncthreads();

    float* outp = out + (size_t)tile * TILE_ROWS * G_DIM;
    #pragma unroll
    for (int i = 0; i < 16; ++i) {
        int e = tid + i * NTHREADS;               // 0..4095 float4
        int r = e >> 5, c4 = e & 31;
        const float* s = &Ssc[r * SSC_PITCH + c4 * 4];
        st_cs4(&outp[e * 4], make_float4(s[0], s[1], s[2], s[3]));
    }
    if (write_tail && tile == NUM_TILES - 1 && tid < G_DIM)
        out[(size_t)W_TOTAL * G_DIM + tid] = incl;
}

extern "C" void kernel_launch(void* const* d_in, const int* in_sizes, int n_in,
                              void* d_out, int out_size) {
    const float* local = (const float*)d_in[0];  // [262144, 512]
    const float* gfeat = (const float*)d_in[1];  // [1, 128]
    const float* W1    = (const float*)d_in[2];  // [512, 128]
    const float* b1    = (const float*)d_in[3];  // [128]
    float* out = (float*)d_out;

    static int configured = 0;
    if (!configured) {
        cudaFuncSetAttribute(key_pool_mma,
                             cudaFuncAttributeMaxDynamicSharedMemorySize, SMEM_TOTAL);
        configured = 1;
    }
    int write_tail = (out_size >= W_TOTAL * G_DIM + G_DIM) ? 1 : 0;

    prep_kernel<<<256, 256>>>(W1);
    key_pool_mma<<<NUM_TILES, NTHREADS, SMEM_TOTAL>>>(local, gfeat, b1, out, write_tail);
}

// round 17
// speedup vs baseline: 1.6202x; 1.0756x over previous
#include <cuda_runtime.h>
#include <cuda_fp16.h>
#include <cstdint>
#include <cfloat>

#define W_TOTAL   262144
#define L_DIM     512
#define G_DIM     128
#define TILE_ROWS 128
#define NUM_TILES (W_TOTAL / TILE_ROWS)   // 2048
#define NKCH      8                       // K chunks of 64
#define NTHREADS  256

// ---- smem layout (bytes), dynamic smem only ----
#define OFF_RAW    0                  // raw fp32 A chunk [128][64] = 32 KB (single)
#define OFF_AH0    32768              // A fp16 [128][64], double, 16 KB each
#define OFF_AH1    49152
#define OFF_B0     65536              // B fp16 [128n][64k], double, 16 KB each
#define OFF_B1     81920              // GEMM region ends 98304
#define OFF_SSC    0                  // epilogue reuse: float[128][132] = 67584
#define SSC_PITCH  132
#define OFF_SWA    67584              // rowgroup aggregates [4][128] f32 = 2 KB
#define OFF_SPRE   69632              // tile prefix 128 f32
#define OFF_STATE  70144              // lookback state (int)
#define SMEM_TOTAL 98304

// device globals (no runtime allocation allowed)
__device__ __half g_Wh[G_DIM * L_DIM];          // W1^T fp16, [n][k] k-major
__device__ float  g_aggregate[NUM_TILES * G_DIM];
__device__ float  g_inclusive[NUM_TILES * G_DIM];
__device__ int    g_flags[NUM_TILES];

#define SW128(o) ((o) ^ (((o) >> 3) & 0x70))

// ---- PTX helpers ----
__device__ __forceinline__ uint32_t smem_u32(const void* p) {
    uint32_t a;
    asm("{ .reg .u64 t; cvta.to.shared.u64 t, %1; cvt.u32.u64 %0, t; }" : "=r"(a) : "l"(p));
    return a;
}
__device__ __forceinline__ void ldsm_x4(uint32_t& r0, uint32_t& r1, uint32_t& r2,
                                        uint32_t& r3, uint32_t addr) {
    asm volatile("ldmatrix.sync.aligned.m8n8.x4.shared.b16 {%0,%1,%2,%3}, [%4];"
                 : "=r"(r0), "=r"(r1), "=r"(r2), "=r"(r3) : "r"(addr));
}
__device__ __forceinline__ void mma_f16(float* c, const uint32_t* a, uint32_t b0, uint32_t b1) {
    asm volatile(
        "mma.sync.aligned.m16n8k16.row.col.f32.f16.f16.f32 "
        "{%0,%1,%2,%3}, {%4,%5,%6,%7}, {%8,%9}, {%0,%1,%2,%3};"
        : "+f"(c[0]), "+f"(c[1]), "+f"(c[2]), "+f"(c[3])
        : "r"(a[0]), "r"(a[1]), "r"(a[2]), "r"(a[3]), "r"(b0), "r"(b1));
}
__device__ __forceinline__ void cp_async16(uint32_t dst, const void* src) {
    asm volatile("cp.async.cg.shared.global [%0], [%1], 16;" :: "r"(dst), "l"(src));
}
#define CP_COMMIT() asm volatile("cp.async.commit_group;" ::: "memory")
#define CP_WAIT0()  asm volatile("cp.async.wait_group 0;" ::: "memory")

__device__ __forceinline__ int ld_flag_cg(const int* p) {
    int f; asm volatile("ld.global.cg.b32 %0, [%1];" : "=r"(f) : "l"(p)); return f;
}
__device__ __forceinline__ float ld_f_cg(const float* p) {
    float f; asm volatile("ld.global.cg.f32 %0, [%1];" : "=f"(f) : "l"(p)); return f;
}
__device__ __forceinline__ void st_cs4(float* p, float4 v) {
    asm volatile("st.global.cs.v4.f32 [%0], {%1,%2,%3,%4};"
                 :: "l"(p), "f"(v.x), "f"(v.y), "f"(v.z), "f"(v.w) : "memory");
}

// ---- merged prep kernel: W1 -> fp16 transpose, zero flags ----
__global__ void prep_kernel(const float* __restrict__ W1) {   // W1: [512][128]
    int idx = blockIdx.x * 256 + threadIdx.x;                 // 65536
    int k = idx >> 7, n = idx & 127;
    g_Wh[n * L_DIM + k] = __float2half_rn(W1[idx]);
    if (idx < NUM_TILES) g_flags[idx] = 0;
}

// ---- main fused kernel: 1-barrier/chunk (self-owned convert) + cummax ----
__global__ void __launch_bounds__(NTHREADS, 2)
key_pool_mma(const float* __restrict__ A,      // [W, L]
             const float* __restrict__ gfeat,  // [G]
             const float* __restrict__ b1,     // [G]
             float* __restrict__ out, int write_tail) {
    extern __shared__ char sm[];
    const uint32_t smb = smem_u32(sm);
    float* Ssc   = (float*)(sm + OFF_SSC);
    float* Swa   = (float*)(sm + OFF_SWA);
    float* Spre  = (float*)(sm + OFF_SPRE);
    int*   Sstat = (int*)(sm + OFF_STATE);

    const int tid  = threadIdx.x;
    const int wid  = tid >> 5;
    const int lane = tid & 31;
    const int tile = blockIdx.x;

    const int rg = wid & 3;          // rowgroup 0..3 (32 rows each)
    const int Rw = rg * 32;          // warp row base
    const int Cw = (wid >> 2) * 64;  // warp col base (0 or 64)
    const int g  = lane >> 2;        // 0..7
    const int cq = (lane & 3) * 2;
    const int l4 = lane & 3;

    const float4* A4 = (const float4*)(A + (size_t)tile * TILE_ROWS * L_DIM);
    const __half* Wh = g_Wh;

    // staging coords: thread owns 32B pairs o = tid + i*256 -> raw bytes [o*32, o*32+32)
    // o -> row r = o>>3, out-block m = o&7 (columns 8m..8m+7), global q = 2m, 2m+1

    // ---- prologue: cp.async raw A(0) fp32 (self-owned pairs) + B(0) ----
    #pragma unroll
    for (int i = 0; i < 4; ++i) {
        int o = tid + i * NTHREADS;              // 0..1023 pairs
        int r = o >> 3, m = o & 7;
        const float4* src = &A4[r * 128 + 2 * m];
        cp_async16(smb + OFF_RAW + o * 32,      src);
        cp_async16(smb + OFF_RAW + o * 32 + 16, src + 1);
    }
    #pragma unroll
    for (int i = 0; i < 4; ++i) {
        int e = tid + i * NTHREADS, n = e >> 3, u = e & 7;
        cp_async16(smb + OFF_B0 + SW128((uint32_t)(n * 128 + u * 16)),
                   Wh + n * L_DIM + u * 8);
    }
    CP_COMMIT();

    // accumulators init with bias: proj = A*W + b
    float acc[2][8][4];
    #pragma unroll
    for (int nt = 0; nt < 8; ++nt) {
        float2 b2 = *(const float2*)&b1[Cw + nt * 8 + cq];
        #pragma unroll
        for (int t = 0; t < 2; ++t) {
            acc[t][nt][0] = b2.x; acc[t][nt][1] = b2.y;
            acc[t][nt][2] = b2.x; acc[t][nt][3] = b2.y;
        }
    }

    // ldmatrix per-thread offsets
    const int a_row  = (lane & 15);
    const int a_kb   = (lane >> 4) << 4;
    const int b_nrow = ((lane >> 4) & 1) * 8 + (lane & 7);
    const int b_kb   = ((lane >> 3) & 1) << 4;

    // ---- mainloop: 8 chunks, ONE barrier each ----
    #pragma unroll
    for (int kc = 0; kc < NKCH; ++kc) {
        const uint32_t ahb = smb + ((kc & 1) ? OFF_AH1 : OFF_AH0);
        char*          ahp = sm + ((kc & 1) ? OFF_AH1 : OFF_AH0);
        const uint32_t bbb = smb + ((kc & 1) ? OFF_B1 : OFF_B0);

        CP_WAIT0();          // OWN raw(kc) pairs + B parts landed

        // convert raw(kc) fp32 -> Ah[kc&1]: reads ONLY self-staged data (race-free)
        #pragma unroll
        for (int i = 0; i < 4; ++i) {
            int o = tid + i * NTHREADS;
            int r = o >> 3, m = o & 7;
            float4 v0 = *(const float4*)(sm + OFF_RAW + o * 32);
            float4 v1 = *(const float4*)(sm + OFF_RAW + o * 32 + 16);
            __half2 h0 = __float22half2_rn(make_float2(v0.x, v0.y));
            __half2 h1 = __float22half2_rn(make_float2(v0.z, v0.w));
            __half2 h2 = __float22half2_rn(make_float2(v1.x, v1.y));
            __half2 h3 = __float22half2_rn(make_float2(v1.z, v1.w));
            *(uint4*)(ahp + SW128((uint32_t)(r * 128 + m * 16))) =
                make_uint4(*(uint32_t*)&h0, *(uint32_t*)&h1,
                           *(uint32_t*)&h2, *(uint32_t*)&h3);
        }
        __syncthreads();     // Ah(kc)+B(kc) global; converts done (raw free);
                             // MMA(kc-1) complete (B[(kc+1)&1] overwrite safe)

        // prefetch raw A(kc+1) (self-owned pairs) + B(kc+1)
        if (kc < NKCH - 1) {
            #pragma unroll
            for (int i = 0; i < 4; ++i) {
                int o = tid + i * NTHREADS;
                int r = o >> 3, m = o & 7;
                const float4* src = &A4[r * 128 + (kc + 1) * 16 + 2 * m];
                cp_async16(smb + OFF_RAW + o * 32,      src);
                cp_async16(smb + OFF_RAW + o * 32 + 16, src + 1);
            }
            const uint32_t bnext = smb + (((kc + 1) & 1) ? OFF_B1 : OFF_B0);
            #pragma unroll
            for (int i = 0; i < 4; ++i) {
                int e = tid + i * NTHREADS, n = e >> 3, u = e & 7;
                cp_async16(bnext + SW128((uint32_t)(n * 128 + u * 16)),
                           Wh + n * L_DIM + (kc + 1) * 64 + u * 8);
            }
            CP_COMMIT();
        }

        // ---- MMA over 4 k16 steps (warp tile 32x64) ----
        #pragma unroll
        for (int j = 0; j < 4; ++j) {
            const int kstep = j * 32;
            uint32_t ah[2][4];
            #pragma unroll
            for (int t = 0; t < 2; ++t) {
                uint32_t offA = (uint32_t)((Rw + t * 16 + a_row) * 128 + kstep + a_kb);
                ldsm_x4(ah[t][0], ah[t][1], ah[t][2], ah[t][3], ahb + SW128(offA));
            }
            #pragma unroll
            for (int nt2 = 0; nt2 < 4; ++nt2) {
                uint32_t offB = (uint32_t)((Cw + nt2 * 16 + b_nrow) * 128 + kstep + b_kb);
                uint32_t bf[4];
                ldsm_x4(bf[0], bf[1], bf[2], bf[3], bbb + SW128(offB));
                #pragma unroll
                for (int half = 0; half < 2; ++half) {
                    const int nt = nt2 * 2 + half;
                    #pragma unroll
                    for (int t = 0; t < 2; ++t)
                        mma_f16(acc[t][nt], ah[t], bf[half * 2], bf[half * 2 + 1]);
                }
            }
        }
    }

    // ---- in-register column cummax over warp's 32 rows ----
    #pragma unroll
    for (int nt = 0; nt < 8; ++nt) {
        #pragma unroll
        for (int t = 0; t < 2; ++t) {
            float c0 = acc[t][nt][0], c1 = acc[t][nt][1];
            float c2 = acc[t][nt][2], c3 = acc[t][nt][3];
            #pragma unroll
            for (int d = 1; d < 8; d <<= 1) {
                float t0 = __shfl_up_sync(0xffffffffu, c0, d * 4);
                float t1 = __shfl_up_sync(0xffffffffu, c1, d * 4);
                float t2 = __shfl_up_sync(0xffffffffu, c2, d * 4);
                float t3 = __shfl_up_sync(0xffffffffu, c3, d * 4);
                if (g >= d) {
                    c0 = fmaxf(c0, t0); c1 = fmaxf(c1, t1);
                    c2 = fmaxf(c2, t2); c3 = fmaxf(c3, t3);
                }
            }
            float f0 = __shfl_sync(0xffffffffu, c0, 28 + l4);
            float f1 = __shfl_sync(0xffffffffu, c1, 28 + l4);
            c2 = fmaxf(c2, f0); c3 = fmaxf(c3, f1);
            acc[t][nt][0] = c0; acc[t][nt][1] = c1;
            acc[t][nt][2] = c2; acc[t][nt][3] = c3;
        }
        // fold t=0 16-row total into t=1 (rows 16..31)
        float tt0 = __shfl_sync(0xffffffffu, acc[0][nt][2], 28 + l4);
        float tt1 = __shfl_sync(0xffffffffu, acc[0][nt][3], 28 + l4);
        acc[1][nt][0] = fmaxf(acc[1][nt][0], tt0);
        acc[1][nt][1] = fmaxf(acc[1][nt][1], tt1);
        acc[1][nt][2] = fmaxf(acc[1][nt][2], tt0);
        acc[1][nt][3] = fmaxf(acc[1][nt][3], tt1);
        if (g == 7)
            *(float2*)&Swa[rg * G_DIM + Cw + nt * 8 + cq] =
                make_float2(acc[1][nt][2], acc[1][nt][3]);
    }
    __syncthreads();   // all MMA/LDSM done before Ssc overwrites GEMM smem

    // ---- earlier-rowgroup prefixes ----
    #pragma unroll
    for (int nt = 0; nt < 8; ++nt) {
        float p0 = -FLT_MAX, p1 = -FLT_MAX;
        for (int q = 0; q < rg; ++q) {
            float2 w = *(float2*)&Swa[q * G_DIM + Cw + nt * 8 + cq];
            p0 = fmaxf(p0, w.x); p1 = fmaxf(p1, w.y);
        }
        #pragma unroll
        for (int t = 0; t < 2; ++t) {
            acc[t][nt][0] = fmaxf(acc[t][nt][0], p0);
            acc[t][nt][1] = fmaxf(acc[t][nt][1], p1);
            acc[t][nt][2] = fmaxf(acc[t][nt][2], p0);
            acc[t][nt][3] = fmaxf(acc[t][nt][3], p1);
        }
    }

    // tile column aggregate (4 rowgroups)
    float tot = -FLT_MAX;
    if (tid < G_DIM) {
        #pragma unroll
        for (int q = 0; q < 4; ++q) tot = fmaxf(tot, Swa[q * G_DIM + tid]);
    }

    // ---- decoupled lookback (32-wide window) ----
    float incl = -FLT_MAX;
    if (tile == 0) {
        if (tid < G_DIM) {
            float run = __ldg(&gfeat[tid]);       // global-feature seed
            incl = fmaxf(tot, run);
            g_inclusive[tid] = incl;
            Spre[tid] = run;
        }
        __threadfence();
        __syncthreads();
        if (tid == 0) atomicExch(&g_flags[0], 2);
    } else {
        if (tid < G_DIM) g_aggregate[(size_t)tile * G_DIM + tid] = tot;
        __threadfence();
        __syncthreads();
        if (tid == 0) atomicExch(&g_flags[tile], 1);

        float run = -FLT_MAX;
        int p = tile - 1;
        while (true) {
            if (wid == 0) {
                int idx = p - lane;
                int f = 1;
                if (idx >= 0) {
                    f = ld_flag_cg(&g_flags[idx]);
                    while (f == 0) { __nanosleep(32); f = ld_flag_cg(&g_flags[idx]); }
                }
                unsigned ball = __ballot_sync(0xffffffffu, f == 2);
                if (lane == 0)
                    Sstat[0] = (ball == 0) ? 32 : (__ffs(ball) - 1);
            }
            __syncthreads();
            int l2 = Sstat[0];
            int lstop = (l2 < 32) ? l2 : 31;
            if (tid < G_DIM) {
                for (int l = 0; l <= lstop; ++l) {
                    int idx = p - l;
                    const float* src = (l == l2) ? &g_inclusive[(size_t)idx * G_DIM]
                                                 : &g_aggregate[(size_t)idx * G_DIM];
                    run = fmaxf(run, ld_f_cg(&src[tid]));
                }
            }
            __syncthreads();
            if (l2 < 32) break;
            p -= 32;
        }
        if (tid < G_DIM) {
            incl = fmaxf(run, tot);
            g_inclusive[(size_t)tile * G_DIM + tid] = incl;
            Spre[tid] = run;
        }
        __threadfence();
        __syncthreads();
        if (tid == 0) atomicExch(&g_flags[tile], 2);
    }
    __syncthreads();

    // ---- combine with tile prefix into Ssc, then staged float4 stores ----
    #pragma unroll
    for (int nt = 0; nt < 8; ++nt) {
        int col = Cw + nt * 8 + cq;
        float2 pp = *(float2*)&Spre[col];
        #pragma unroll
        for (int t = 0; t < 2; ++t) {
            int r0 = Rw + t * 16 + g;
            *(float2*)&Ssc[r0 * SSC_PITCH + col] =
                make_float2(fmaxf(acc[t][nt][0], pp.x), fmaxf(acc[t][nt][1], pp.y));
            *(float2*)&Ssc[(r0 + 8) * SSC_PITCH + col] =
                make_float2(fmaxf(acc[t][nt][2], pp.x), fmaxf(acc[t][nt][3], pp.y));
        }
    }
    __syncthreads();

    float* outp = out + (size_t)tile * TILE_ROWS * G_DIM;
    #pragma unroll
    for (int i = 0; i < 16; ++i) {
        int e = tid + i * NTHREADS;               // 0..4095 float4
        int r = e >> 5, c4 = e & 31;
        const float* s = &Ssc[r * SSC_PITCH + c4 * 4];
        st_cs4(&outp[e * 4], make_float4(s[0], s[1], s[2], s[3]));
    }
    if (write_tail && tile == NUM_TILES - 1 && tid < G_DIM)
        out[(size_t)W_TOTAL * G_DIM + tid] = incl;
}

extern "C" void kernel_launch(void* const* d_in, const int* in_sizes, int n_in,
                              void* d_out, int out_size) {
    const float* local = (const float*)d_in[0];  // [262144, 512]
    const float* gfeat = (const float*)d_in[1];  // [1, 128]
    const float* W1    = (const float*)d_in[2];  // [512, 128]
    const float* b1    = (const float*)d_in[3];  // [128]
    float* out = (float*)d_out;

    static int configured = 0;
    if (!configured) {
        cudaFuncSetAttribute(key_pool_mma,
                             cudaFuncAttributeMaxDynamicSharedMemorySize, SMEM_TOTAL);
        configured = 1;
    }
    int write_tail = (out_size >= W_TOTAL * G_DIM + G_DIM) ? 1 : 0;

    prep_kernel<<<256, 256>>>(W1);
    key_pool_mma<<<NUM_TILES, NTHREADS, SMEM_TOTAL>>>(local, gfeat, b1, out, write_tail);
}